// round 2
// baseline (speedup 1.0000x reference)
#include <cuda_runtime.h>
#include <cuda_bf16.h>
#include <float.h>

// ---------------- problem constants ----------------
#define NQ      2048      // queries
#define DIMS    128       // feature dim
#define MTRAIN  100000    // train points
#define KNB     16        // neighbors
#define NC      10        // classes

#define NSPLIT  9         // train splits (16 qtiles * 9 = 144 blocks ~ 1 wave)
#define SPLIT   11112     // ceil(100000/9)
#define QTILE   128
#define CHUNK   128

// smem layout (bytes)
#define AS_OFF   0
#define AS_PITCH 130                       // floats per query row (65 doubles)
#define AS_BYTES (128*AS_PITCH*4)          // 66560
#define BS_OFF   (AS_OFF + AS_BYTES)       // 66560
#define BS_BYTES (128*128*4)               // 65536 (also reused as the score tile Ds)
#define T2_OFF   (BS_OFF + BS_BYTES)       // 132096
#define T2_BYTES (128*4)
#define TV_OFF   (T2_OFF + T2_BYTES)       // 132608
#define TV_BYTES (16*256*4)
#define TI_OFF   (TV_OFF + TV_BYTES)       // 148992
#define TI_BYTES (16*256*4)
#define SMEM_TOTAL (TI_OFF + TI_BYTES)     // 165376

// ---------------- scratch (__device__ globals; no allocation) ----------------
__device__ float g_t2[MTRAIN];
__device__ float g_x2[NQ];
__device__ float g_topd[NQ * NSPLIT * 32];
__device__ int   g_topi[NQ * NSPLIT * 32];

// packed dual-FMA: d = {d.lo + a.lo*b.lo, d.hi + a.hi*b.hi}
__device__ __forceinline__ void ffma2(unsigned long long& d,
                                      unsigned long long a,
                                      unsigned long long b) {
    asm("fma.rn.f32x2 %0, %1, %2, %0;" : "+l"(d) : "l"(a), "l"(b));
}

// ---------------- kernel 1: squared norms of train rows and query rows ----------------
__global__ void norms_kernel(const float* __restrict__ x,
                             const float* __restrict__ train) {
    int warp = (blockIdx.x * blockDim.x + threadIdx.x) >> 5;
    int lane = threadIdx.x & 31;
    if (warp >= MTRAIN + NQ) return;
    const float* src = (warp < MTRAIN) ? (train + (size_t)warp * DIMS)
                                       : (x + (size_t)(warp - MTRAIN) * DIMS);
    float4 v = ((const float4*)src)[lane];
    float s = v.x*v.x + v.y*v.y + v.z*v.z + v.w*v.w;
    #pragma unroll
    for (int o = 16; o > 0; o >>= 1) s += __shfl_down_sync(0xffffffffu, s, o);
    if (lane == 0) {
        if (warp < MTRAIN) g_t2[warp] = s;
        else               g_x2[warp - MTRAIN] = s;
    }
}

// ---------------- kernel 2: fused distance GEMM + per-split top-16 ----------------
__global__ __launch_bounds__(256, 1)
void knn_kernel(const float* __restrict__ x,
                const float* __restrict__ train) {
    extern __shared__ char sm[];
    float* As  = (float*)(sm + AS_OFF);
    float* Bs  = (float*)(sm + BS_OFF);   // doubles as the score tile after compute
    float* t2s = (float*)(sm + T2_OFF);
    float* stv = (float*)(sm + TV_OFF);
    int*   sti = (int*)(sm + TI_OFF);

    const int tid = threadIdx.x;
    const int split = blockIdx.x;
    const int qt    = blockIdx.y;
    const int split_start = split * SPLIT;
    const int split_end   = min(split_start + SPLIT, MTRAIN);
    const int nch = (split_end - split_start + CHUNK - 1) / CHUNK;

    const int tx = tid & 15, ty = tid >> 4;
    const int q0 = ty * 8, c0 = tx * 8;

    // init top-k lists (persistent across chunks)
    #pragma unroll
    for (int j = 0; j < 16; j++) { stv[j*256 + tid] = FLT_MAX; sti[j*256 + tid] = 0; }
    float vmax = FLT_MAX; int maxslot = 0;

    // load the query tile once: As[q][k], pitch 130 floats
    #pragma unroll
    for (int i = 0; i < 16; i++) {
        int e = tid + i * 256;
        int q = e >> 5, k4 = e & 31;
        float4 v = ((const float4*)x)[(size_t)(qt*QTILE + q) * 32 + k4];
        float* dst = As + q * AS_PITCH + k4 * 4;
        dst[0] = v.x; dst[1] = v.y; dst[2] = v.z; dst[3] = v.w;
    }

    const int scan_q   = tid >> 1;          // each query served by 2 threads
    const int scan_h   = tid & 1;
    const int scan_swz = scan_q & 31;

    for (int ch = 0; ch < nch; ch++) {
        const int cb = split_start + ch * CHUNK;

        // ---- load B chunk (XOR-swizzled on 8B slots) + t2 chunk ----
        #pragma unroll
        for (int i = 0; i < 16; i++) {
            int e = tid + i * 256;
            int c = e >> 5, k4 = e & 31;
            int row = cb + c;
            float4 v = make_float4(0.f, 0.f, 0.f, 0.f);
            if (row < split_end) v = ((const float4*)train)[(size_t)row * 32 + k4];
            int xsw = (c >> 3) & 15;
            float2* b2 = (float2*)Bs;
            int d0 = 2 * k4;
            b2[c*64 + ( d0      ^ xsw)] = make_float2(v.x, v.y);
            b2[c*64 + ((d0 + 1) ^ xsw)] = make_float2(v.z, v.w);
        }
        if (tid < 128) {
            int row = cb + tid;
            t2s[tid] = (row < split_end) ? g_t2[row] : 0.f;
        }
        __syncthreads();

        // ---- GEMM: acc{q,c} = {sum over even k, sum over odd k} ----
        unsigned long long acc[8][8];
        #pragma unroll
        for (int i = 0; i < 8; i++)
            #pragma unroll
            for (int j = 0; j < 8; j++) acc[i][j] = 0ull;

        const unsigned long long* A8 = (const unsigned long long*)As; // idx: q*65 + kk
        const unsigned long long* B8 = (const unsigned long long*)Bs; // idx: c*64 + (kk^tx)

        #pragma unroll 2
        for (int kk = 0; kk < 64; kk++) {
            unsigned long long aF[8], bF[8];
            int off = kk ^ tx;
            #pragma unroll
            for (int i = 0; i < 8; i++) aF[i] = A8[(q0 + i) * 65 + kk];
            #pragma unroll
            for (int j = 0; j < 8; j++) bF[j] = B8[(c0 + j) * 64 + off];
            #pragma unroll
            for (int i = 0; i < 8; i++)
                #pragma unroll
                for (int j = 0; j < 8; j++) ffma2(acc[i][j], aF[i], bF[j]);
        }
        __syncthreads();

        // ---- write score tile s = t2 - 2*dot over Bs (XOR swizzle by q&31) ----
        #pragma unroll
        for (int i = 0; i < 8; i++) {
            int q = q0 + i, yq = q & 31;
            #pragma unroll
            for (int j = 0; j < 8; j++) {
                int c = c0 + j;
                union { unsigned long long u; float2 f; } cv; cv.u = acc[i][j];
                float dot = cv.f.x + cv.f.y;
                Bs[q * 128 + (c ^ yq)] = t2s[c] - 2.0f * dot;
            }
        }
        __syncthreads();

        // ---- scan: maintain top-16 smallest scores per (query, half) ----
        {
            const float* row = Bs + scan_q * 128;
            const int base = scan_h * 64;
            const int gbase = cb + base;
            for (int cc = 0; cc < 64; cc++) {
                int gcol = gbase + cc;
                float v = row[(base + cc) ^ scan_swz];
                if (gcol < split_end && v < vmax) {
                    stv[maxslot*256 + tid] = v;
                    sti[maxslot*256 + tid] = gcol;
                    float nm = stv[0*256 + tid]; int np = 0;
                    #pragma unroll
                    for (int j = 1; j < 16; j++) {
                        float tj = stv[j*256 + tid];
                        if (tj > nm) { nm = tj; np = j; }
                    }
                    vmax = nm; maxslot = np;
                }
            }
        }
        __syncthreads();
    }

    // ---- dump this block's candidates to global scratch ----
    {
        int qg = qt * QTILE + scan_q;
        int base = (qg * NSPLIT + split) * 32 + scan_h * 16;
        #pragma unroll
        for (int j = 0; j < 16; j++) {
            g_topd[base + j] = stv[j*256 + tid];
            g_topi[base + j] = sti[j*256 + tid];
        }
    }
}

// ---------------- kernel 3: merge 288 candidates/query, weighted vote ----------------
__global__ void finalize_kernel(const int* __restrict__ labels,
                                float* __restrict__ pred_out,
                                float* __restrict__ proba_out) {
    int warp = threadIdx.x >> 5, lane = threadIdx.x & 31;
    int q = blockIdx.x * 8 + warp;

    float cv[9]; int ci[9];
    const float* td = g_topd + (size_t)q * (NSPLIT * 32);
    const int*   ti = g_topi + (size_t)q * (NSPLIT * 32);
    #pragma unroll
    for (int t = 0; t < 9; t++) { cv[t] = td[lane + 32*t]; ci[t] = ti[lane + 32*t]; }

    float x2 = g_x2[q];
    float proba[NC], pz[NC];
    #pragma unroll
    for (int c = 0; c < NC; c++) { proba[c] = 0.f; pz[c] = 0.f; }
    bool anyz = false;

    for (int r = 0; r < KNB; r++) {
        // lane-local min
        float mv = cv[0]; int ms = 0;
        #pragma unroll
        for (int t = 1; t < 9; t++) if (cv[t] < mv) { mv = cv[t]; ms = t; }
        float rv = mv; int ridx = ci[ms]; int rlane = lane;
        // fix up ridx for tracked slot (ci[ms] with ms dynamic -> unrolled select)
        #pragma unroll
        for (int t = 0; t < 9; t++) if (t == ms) ridx = ci[t];
        #pragma unroll
        for (int o = 16; o > 0; o >>= 1) {
            float ov = __shfl_down_sync(0xffffffffu, rv, o);
            int   oi = __shfl_down_sync(0xffffffffu, ridx, o);
            int   ol = __shfl_down_sync(0xffffffffu, rlane, o);
            if (ov < rv) { rv = ov; ridx = oi; rlane = ol; }
        }
        rv    = __shfl_sync(0xffffffffu, rv, 0);
        ridx  = __shfl_sync(0xffffffffu, ridx, 0);
        rlane = __shfl_sync(0xffffffffu, rlane, 0);
        // winner retires its slot
        #pragma unroll
        for (int t = 0; t < 9; t++)
            if (lane == rlane && t == ms) cv[t] = FLT_MAX;

        float d = sqrtf(fmaxf(x2 + rv, 0.0f));
        int lab = labels[ridx];
        if (d <= 0.0f) {
            anyz = true;
            #pragma unroll
            for (int c = 0; c < NC; c++) pz[c] += (lab == c) ? 1.0f : 0.0f;
        } else {
            float w = 1.0f / d;
            #pragma unroll
            for (int c = 0; c < NC; c++) proba[c] += (lab == c) ? w : 0.0f;
        }
    }

    if (anyz) {
        #pragma unroll
        for (int c = 0; c < NC; c++) proba[c] = pz[c];
    }
    float s = 0.f;
    #pragma unroll
    for (int c = 0; c < NC; c++) s += proba[c];
    if (s == 0.f) s = 1.f;
    float inv = 1.f / s;

    int best = 0; float bv = proba[0];
    #pragma unroll
    for (int c = 1; c < NC; c++) if (proba[c] > bv) { bv = proba[c]; best = c; }

    if (lane == 0) {
        if (pred_out)  pred_out[q] = (float)best;
        if (proba_out) {
            #pragma unroll
            for (int c = 0; c < NC; c++) proba_out[q * NC + c] = proba[c] * inv;
        }
    }
}

// ---------------- launch ----------------
extern "C" void kernel_launch(void* const* d_in, const int* in_sizes, int n_in,
                              void* d_out, int out_size) {
    const float* x      = (const float*)d_in[0];
    const float* train  = (const float*)d_in[1];
    const int*   labels = (const int*)d_in[2];
    float* out = (float*)d_out;

    float* pred_out  = nullptr;
    float* proba_out = nullptr;
    if (out_size >= NQ * (NC + 1)) { pred_out = out; proba_out = out + NQ; }
    else if (out_size == NQ * NC)  { proba_out = out; }
    else                           { pred_out = out; }

    cudaFuncSetAttribute(knn_kernel, cudaFuncAttributeMaxDynamicSharedMemorySize, SMEM_TOTAL);

    norms_kernel<<<(MTRAIN + NQ + 7) / 8, 256>>>(x, train);
    knn_kernel<<<dim3(NSPLIT, NQ / QTILE), 256, SMEM_TOTAL>>>(x, train);
    finalize_kernel<<<NQ / 8, 256>>>(labels, pred_out, proba_out);
}

// round 3
// speedup vs baseline: 1.0008x; 1.0008x over previous
#include <cuda_runtime.h>
#include <cuda_bf16.h>
#include <float.h>

// ---------------- problem constants ----------------
#define NQ      2048      // queries
#define DIMS    128       // feature dim
#define MTRAIN  100000    // train points
#define KNB     16        // neighbors
#define NC      10        // classes

#define NSPLIT  9         // train splits (16 qtiles * 9 = 144 blocks ~ 1 wave)
#define SPLIT   11112     // ceil(100000/9)
#define QTILE   128
#define CHUNK   128

// smem layout (bytes)
#define AS_OFF   0
#define AS_PITCH 130                       // floats per query row (65 doubles)
#define AS_BYTES (128*AS_PITCH*4)          // 66560
#define BS_OFF   (AS_OFF + AS_BYTES)       // 66560
#define BS_BYTES (128*128*4)               // 65536 (also reused as the score tile Ds)
#define T2_OFF   (BS_OFF + BS_BYTES)       // 132096
#define T2_BYTES (128*4)
#define TV_OFF   (T2_OFF + T2_BYTES)       // 132608
#define TV_BYTES (16*256*4)
#define TI_OFF   (TV_OFF + TV_BYTES)       // 148992
#define TI_BYTES (16*256*4)
#define SMEM_TOTAL (TI_OFF + TI_BYTES)     // 165376

// ---------------- scratch (__device__ globals; no allocation) ----------------
__device__ float g_t2[MTRAIN];
__device__ float g_x2[NQ];
__device__ float g_topd[NQ * NSPLIT * 32];
__device__ int   g_topi[NQ * NSPLIT * 32];

// packed dual-FMA: d = {d.lo + a.lo*b.lo, d.hi + a.hi*b.hi}
__device__ __forceinline__ void ffma2(unsigned long long& d,
                                      unsigned long long a,
                                      unsigned long long b) {
    asm("fma.rn.f32x2 %0, %1, %2, %0;" : "+l"(d) : "l"(a), "l"(b));
}

// ---------------- kernel 1: squared norms of train rows and query rows ----------------
__global__ void norms_kernel(const float* __restrict__ x,
                             const float* __restrict__ train) {
    int warp = (blockIdx.x * blockDim.x + threadIdx.x) >> 5;
    int lane = threadIdx.x & 31;
    if (warp >= MTRAIN + NQ) return;
    const float* src = (warp < MTRAIN) ? (train + (size_t)warp * DIMS)
                                       : (x + (size_t)(warp - MTRAIN) * DIMS);
    float4 v = ((const float4*)src)[lane];
    float s = v.x*v.x + v.y*v.y + v.z*v.z + v.w*v.w;
    #pragma unroll
    for (int o = 16; o > 0; o >>= 1) s += __shfl_down_sync(0xffffffffu, s, o);
    if (lane == 0) {
        if (warp < MTRAIN) g_t2[warp] = s;
        else               g_x2[warp - MTRAIN] = s;
    }
}

// ---------------- kernel 2: fused distance GEMM + per-split top-16 ----------------
__global__ __launch_bounds__(256, 1)
void knn_kernel(const float* __restrict__ x,
                const float* __restrict__ train) {
    extern __shared__ char sm[];
    float* As  = (float*)(sm + AS_OFF);
    float* Bs  = (float*)(sm + BS_OFF);   // doubles as the score tile after compute
    float* t2s = (float*)(sm + T2_OFF);
    float* stv = (float*)(sm + TV_OFF);
    int*   sti = (int*)(sm + TI_OFF);

    const int tid = threadIdx.x;
    const int split = blockIdx.x;
    const int qt    = blockIdx.y;
    const int split_start = split * SPLIT;
    const int split_end   = min(split_start + SPLIT, MTRAIN);
    const int nch = (split_end - split_start + CHUNK - 1) / CHUNK;

    const int tx = tid & 15, ty = tid >> 4;
    const int q0 = ty * 8, c0 = tx * 8;

    // init top-k lists (persistent across chunks)
    #pragma unroll
    for (int j = 0; j < 16; j++) { stv[j*256 + tid] = FLT_MAX; sti[j*256 + tid] = 0; }
    float vmax = FLT_MAX; int maxslot = 0;

    // load the query tile once: As[q][k], pitch 130 floats
    #pragma unroll
    for (int i = 0; i < 16; i++) {
        int e = tid + i * 256;
        int q = e >> 5, k4 = e & 31;
        float4 v = ((const float4*)x)[(size_t)(qt*QTILE + q) * 32 + k4];
        float* dst = As + q * AS_PITCH + k4 * 4;
        dst[0] = v.x; dst[1] = v.y; dst[2] = v.z; dst[3] = v.w;
    }

    const int scan_q   = tid >> 1;          // each query served by 2 threads
    const int scan_h   = tid & 1;
    const int scan_swz = scan_q & 31;

    for (int ch = 0; ch < nch; ch++) {
        const int cb = split_start + ch * CHUNK;

        // ---- load B chunk (XOR-swizzled on 8B slots) + t2 chunk ----
        #pragma unroll
        for (int i = 0; i < 16; i++) {
            int e = tid + i * 256;
            int c = e >> 5, k4 = e & 31;
            int row = cb + c;
            float4 v = make_float4(0.f, 0.f, 0.f, 0.f);
            if (row < split_end) v = ((const float4*)train)[(size_t)row * 32 + k4];
            int xsw = (c >> 3) & 15;
            float2* b2 = (float2*)Bs;
            int d0 = 2 * k4;
            b2[c*64 + ( d0      ^ xsw)] = make_float2(v.x, v.y);
            b2[c*64 + ((d0 + 1) ^ xsw)] = make_float2(v.z, v.w);
        }
        if (tid < 128) {
            int row = cb + tid;
            t2s[tid] = (row < split_end) ? g_t2[row] : 0.f;
        }
        __syncthreads();

        // ---- GEMM: acc{q,c} = {sum over even k, sum over odd k} ----
        unsigned long long acc[8][8];
        #pragma unroll
        for (int i = 0; i < 8; i++)
            #pragma unroll
            for (int j = 0; j < 8; j++) acc[i][j] = 0ull;

        const unsigned long long* A8 = (const unsigned long long*)As; // idx: q*65 + kk
        const unsigned long long* B8 = (const unsigned long long*)Bs; // idx: c*64 + (kk^tx)

        #pragma unroll 2
        for (int kk = 0; kk < 64; kk++) {
            unsigned long long aF[8], bF[8];
            int off = kk ^ tx;
            #pragma unroll
            for (int i = 0; i < 8; i++) aF[i] = A8[(q0 + i) * 65 + kk];
            #pragma unroll
            for (int j = 0; j < 8; j++) bF[j] = B8[(c0 + j) * 64 + off];
            #pragma unroll
            for (int i = 0; i < 8; i++)
                #pragma unroll
                for (int j = 0; j < 8; j++) ffma2(acc[i][j], aF[i], bF[j]);
        }
        __syncthreads();

        // ---- write score tile s = t2 - 2*dot over Bs (XOR swizzle by q&31) ----
        #pragma unroll
        for (int i = 0; i < 8; i++) {
            int q = q0 + i, yq = q & 31;
            #pragma unroll
            for (int j = 0; j < 8; j++) {
                int c = c0 + j;
                union { unsigned long long u; float2 f; } cv; cv.u = acc[i][j];
                float dot = cv.f.x + cv.f.y;
                Bs[q * 128 + (c ^ yq)] = t2s[c] - 2.0f * dot;
            }
        }
        __syncthreads();

        // ---- scan: maintain top-16 smallest scores per (query, half) ----
        {
            const float* row = Bs + scan_q * 128;
            const int base = scan_h * 64;
            const int gbase = cb + base;
            for (int cc = 0; cc < 64; cc++) {
                int gcol = gbase + cc;
                float v = row[(base + cc) ^ scan_swz];
                if (gcol < split_end && v < vmax) {
                    stv[maxslot*256 + tid] = v;
                    sti[maxslot*256 + tid] = gcol;
                    float nm = stv[0*256 + tid]; int np = 0;
                    #pragma unroll
                    for (int j = 1; j < 16; j++) {
                        float tj = stv[j*256 + tid];
                        if (tj > nm) { nm = tj; np = j; }
                    }
                    vmax = nm; maxslot = np;
                }
            }
        }
        __syncthreads();
    }

    // ---- dump this block's candidates to global scratch ----
    {
        int qg = qt * QTILE + scan_q;
        int base = (qg * NSPLIT + split) * 32 + scan_h * 16;
        #pragma unroll
        for (int j = 0; j < 16; j++) {
            g_topd[base + j] = stv[j*256 + tid];
            g_topi[base + j] = sti[j*256 + tid];
        }
    }
}

// ---------------- kernel 3: merge 288 candidates/query, weighted vote ----------------
__global__ void finalize_kernel(const int* __restrict__ labels,
                                float* __restrict__ pred_out,
                                float* __restrict__ proba_out) {
    int warp = threadIdx.x >> 5, lane = threadIdx.x & 31;
    int q = blockIdx.x * 8 + warp;

    float cv[9]; int ci[9];
    const float* td = g_topd + (size_t)q * (NSPLIT * 32);
    const int*   ti = g_topi + (size_t)q * (NSPLIT * 32);
    #pragma unroll
    for (int t = 0; t < 9; t++) { cv[t] = td[lane + 32*t]; ci[t] = ti[lane + 32*t]; }

    float x2 = g_x2[q];
    float proba[NC], pz[NC];
    #pragma unroll
    for (int c = 0; c < NC; c++) { proba[c] = 0.f; pz[c] = 0.f; }
    bool anyz = false;

    for (int r = 0; r < KNB; r++) {
        // lane-local min
        float mv = cv[0]; int ms = 0;
        #pragma unroll
        for (int t = 1; t < 9; t++) if (cv[t] < mv) { mv = cv[t]; ms = t; }
        float rv = mv; int ridx = ci[ms]; int rlane = lane;
        // fix up ridx for tracked slot (ci[ms] with ms dynamic -> unrolled select)
        #pragma unroll
        for (int t = 0; t < 9; t++) if (t == ms) ridx = ci[t];
        #pragma unroll
        for (int o = 16; o > 0; o >>= 1) {
            float ov = __shfl_down_sync(0xffffffffu, rv, o);
            int   oi = __shfl_down_sync(0xffffffffu, ridx, o);
            int   ol = __shfl_down_sync(0xffffffffu, rlane, o);
            if (ov < rv) { rv = ov; ridx = oi; rlane = ol; }
        }
        rv    = __shfl_sync(0xffffffffu, rv, 0);
        ridx  = __shfl_sync(0xffffffffu, ridx, 0);
        rlane = __shfl_sync(0xffffffffu, rlane, 0);
        // winner retires its slot
        #pragma unroll
        for (int t = 0; t < 9; t++)
            if (lane == rlane && t == ms) cv[t] = FLT_MAX;

        float d = sqrtf(fmaxf(x2 + rv, 0.0f));
        int lab = labels[ridx];
        if (d <= 0.0f) {
            anyz = true;
            #pragma unroll
            for (int c = 0; c < NC; c++) pz[c] += (lab == c) ? 1.0f : 0.0f;
        } else {
            float w = 1.0f / d;
            #pragma unroll
            for (int c = 0; c < NC; c++) proba[c] += (lab == c) ? w : 0.0f;
        }
    }

    if (anyz) {
        #pragma unroll
        for (int c = 0; c < NC; c++) proba[c] = pz[c];
    }
    float s = 0.f;
    #pragma unroll
    for (int c = 0; c < NC; c++) s += proba[c];
    if (s == 0.f) s = 1.f;
    float inv = 1.f / s;

    int best = 0; float bv = proba[0];
    #pragma unroll
    for (int c = 1; c < NC; c++) if (proba[c] > bv) { bv = proba[c]; best = c; }

    if (lane == 0) {
        if (pred_out)  pred_out[q] = (float)best;
        if (proba_out) {
            #pragma unroll
            for (int c = 0; c < NC; c++) proba_out[q * NC + c] = proba[c] * inv;
        }
    }
}

// ---------------- launch ----------------
extern "C" void kernel_launch(void* const* d_in, const int* in_sizes, int n_in,
                              void* d_out, int out_size) {
    const float* x      = (const float*)d_in[0];
    const float* train  = (const float*)d_in[1];
    const int*   labels = (const int*)d_in[2];
    float* out = (float*)d_out;

    float* pred_out  = nullptr;
    float* proba_out = nullptr;
    if (out_size >= NQ * (NC + 1)) { pred_out = out; proba_out = out + NQ; }
    else if (out_size == NQ * NC)  { proba_out = out; }
    else                           { pred_out = out; }

    cudaFuncSetAttribute(knn_kernel, cudaFuncAttributeMaxDynamicSharedMemorySize, SMEM_TOTAL);

    norms_kernel<<<(MTRAIN + NQ + 7) / 8, 256>>>(x, train);
    knn_kernel<<<dim3(NSPLIT, NQ / QTILE), 256, SMEM_TOTAL>>>(x, train);
    finalize_kernel<<<NQ / 8, 256>>>(labels, pred_out, proba_out);
}

// round 6
// speedup vs baseline: 1.9920x; 1.9903x over previous
#include <cuda_runtime.h>
#include <cuda_bf16.h>
#include <float.h>
#include <stdint.h>

#define NQ      2048
#define DIMS    128
#define MTRAIN  100000
#define KNB     16
#define NC      10
#define NSPLIT  9
#define SPLIT   11112
#define QTILE   128
#define CHUNK   128

// smem map (bytes)
#define SA_HI  0
#define SA_LO  32768
#define SB_HI  65536
#define SB_LO  98304
#define DS_OFF 131072              // 128x128 fp32 score tile (float2-swizzled)
#define T2_OFF 196608              // 2 x 128 floats (ring)
#define STV_OFF 197632             // 16 x 256 floats
#define STI_OFF 214016             // 16 x 256 ints
#define SMEM_TOTAL 230400

__device__ float g_t2[MTRAIN];
__device__ float g_x2[NQ];
__device__ __nv_bfloat16 g_train_hi[(size_t)MTRAIN*DIMS];
__device__ __nv_bfloat16 g_train_lo[(size_t)MTRAIN*DIMS];
__device__ __nv_bfloat16 g_x_hi[NQ*DIMS];
__device__ __nv_bfloat16 g_x_lo[NQ*DIMS];
__device__ float g_topd[NQ * NSPLIT * 32];
__device__ int   g_topi[NQ * NSPLIT * 32];

__device__ __forceinline__ uint32_t smem_u32(const void* p) {
    uint32_t a;
    asm("{ .reg .u64 t; cvta.to.shared.u64 t, %1; cvt.u32.u64 %0, t; }" : "=r"(a) : "l"(p));
    return a;
}
__device__ __forceinline__ void cpa16(uint32_t dst, const void* src) {
    asm volatile("cp.async.cg.shared.global [%0], [%1], 16;" :: "r"(dst), "l"(src));
}
#define CP_COMMIT() asm volatile("cp.async.commit_group;" ::: "memory")
#define CP_WAIT0()  asm volatile("cp.async.wait_group 0;" ::: "memory")

// tile swizzle: 256B rows, XOR 16B-slot bits[4:7) with row%8
__device__ __forceinline__ uint32_t swz(uint32_t off) {
    return off ^ ((off >> 4) & 0x70u);
}
__device__ __forceinline__ uint32_t pkbf(__nv_bfloat16 a, __nv_bfloat16 b) {
    return (uint32_t)__bfloat16_as_ushort(a) | ((uint32_t)__bfloat16_as_ushort(b) << 16);
}

// -------- kernel 1: norms + hi/lo bf16 split --------
__global__ void prep_kernel(const float* __restrict__ x, const float* __restrict__ train) {
    int warp = (blockIdx.x * blockDim.x + threadIdx.x) >> 5;
    int lane = threadIdx.x & 31;
    if (warp >= MTRAIN + NQ) return;
    const float* src; __nv_bfloat16 *dh, *dl; float* t2dst;
    if (warp < MTRAIN) {
        src = train + (size_t)warp * DIMS;
        dh = g_train_hi + (size_t)warp * DIMS; dl = g_train_lo + (size_t)warp * DIMS;
        t2dst = g_t2 + warp;
    } else {
        int q = warp - MTRAIN;
        src = x + (size_t)q * DIMS;
        dh = g_x_hi + (size_t)q * DIMS; dl = g_x_lo + (size_t)q * DIMS;
        t2dst = g_x2 + q;
    }
    float4 v = ((const float4*)src)[lane];
    __nv_bfloat16 h0 = __float2bfloat16(v.x), h1 = __float2bfloat16(v.y);
    __nv_bfloat16 h2 = __float2bfloat16(v.z), h3 = __float2bfloat16(v.w);
    __nv_bfloat16 l0 = __float2bfloat16(v.x - __bfloat162float(h0));
    __nv_bfloat16 l1 = __float2bfloat16(v.y - __bfloat162float(h1));
    __nv_bfloat16 l2 = __float2bfloat16(v.z - __bfloat162float(h2));
    __nv_bfloat16 l3 = __float2bfloat16(v.w - __bfloat162float(h3));
    ((uint2*)dh)[lane] = make_uint2(pkbf(h0, h1), pkbf(h2, h3));
    ((uint2*)dl)[lane] = make_uint2(pkbf(l0, l1), pkbf(l2, l3));
    float s = v.x*v.x + v.y*v.y + v.z*v.z + v.w*v.w;
    #pragma unroll
    for (int o = 16; o > 0; o >>= 1) s += __shfl_down_sync(0xffffffffu, s, o);
    if (lane == 0) *t2dst = s;
}

// one bf16 pass: acc += A(sa) * B(sb)^T over K=128
__device__ __forceinline__ void gemm_pass(uint32_t sa, uint32_t sb,
                                          uint32_t athr, uint32_t bthr, uint32_t xa,
                                          int m0, int n0, float acc[16][4]) {
    #pragma unroll
    for (int kk = 0; kk < 8; kk++) {
        uint32_t a[4][4], b[4][2];
        #pragma unroll
        for (int i = 0; i < 4; i++) {
            uint32_t off = (uint32_t)((m0 + i * 16) * 256) + athr + kk * 32;
            uint32_t ad = sa + (off ^ xa);
            asm volatile("ldmatrix.sync.aligned.m8n8.x4.shared.b16 {%0,%1,%2,%3}, [%4];"
                : "=r"(a[i][0]), "=r"(a[i][1]), "=r"(a[i][2]), "=r"(a[i][3]) : "r"(ad));
        }
        #pragma unroll
        for (int j2 = 0; j2 < 2; j2++) {
            uint32_t off = (uint32_t)(n0 * 256 + j2 * 4096) + bthr + kk * 32;
            uint32_t bd = sb + (off ^ xa);
            asm volatile("ldmatrix.sync.aligned.m8n8.x4.shared.b16 {%0,%1,%2,%3}, [%4];"
                : "=r"(b[j2*2][0]), "=r"(b[j2*2][1]), "=r"(b[j2*2+1][0]), "=r"(b[j2*2+1][1])
                : "r"(bd));
        }
        #pragma unroll
        for (int i = 0; i < 4; i++)
            #pragma unroll
            for (int j = 0; j < 4; j++) {
                float* d = acc[i * 4 + j];
                asm volatile("mma.sync.aligned.m16n8k16.row.col.f32.bf16.bf16.f32 "
                    "{%0,%1,%2,%3}, {%4,%5,%6,%7}, {%8,%9}, {%0,%1,%2,%3};"
                    : "+f"(d[0]), "+f"(d[1]), "+f"(d[2]), "+f"(d[3])
                    : "r"(a[i][0]), "r"(a[i][1]), "r"(a[i][2]), "r"(a[i][3]),
                      "r"(b[j][0]), "r"(b[j][1]));
            }
    }
}

__device__ __forceinline__ void topk_ins(float* stv, int* sti, int tid,
                                         float sc, int gc, float& vmax, int& maxslot) {
    stv[maxslot * 256 + tid] = sc;
    sti[maxslot * 256 + tid] = gc;
    float nm = stv[tid]; int np = 0;
    #pragma unroll
    for (int j = 1; j < 16; j++) {
        float tj = stv[j * 256 + tid];
        if (tj > nm) { nm = tj; np = j; }
    }
    vmax = nm; maxslot = np;
}

// -------- kernel 2: HMMA bf16x3 distance GEMM + fused top-16 --------
__global__ __launch_bounds__(256, 1) void knn_kernel() {
    extern __shared__ char sm[];
    const uint32_t sb = smem_u32(sm);
    float2* Ds2 = (float2*)(sm + DS_OFF);
    float*  t2r = (float*)(sm + T2_OFF);
    float*  stv = (float*)(sm + STV_OFF);
    int*    sti = (int*)(sm + STI_OFF);

    const int tid = threadIdx.x;
    const int wid = tid >> 5;
    const int lane = tid & 31;
    const int split = blockIdx.x;
    const int qt    = blockIdx.y;
    const int split_start = split * SPLIT;
    const int split_end   = min(split_start + SPLIT, MTRAIN);
    const int nch = (split_end - split_start + CHUNK - 1) / CHUNK;

    const int m0 = (wid >> 2) * 64;
    const int n0 = (wid & 3) * 32;
    const uint32_t xa   = (uint32_t)(lane & 7) << 4;
    const uint32_t athr = (uint32_t)((lane & 15) * 256 + ((lane >> 4) & 1) * 16);
    const uint32_t bthr = (uint32_t)((lane & 7) * 256 + ((lane >> 4) & 1) * 2048
                                     + ((lane >> 3) & 1) * 16);

    // prologue: A hi/lo + B(0) hi/lo + t2(0)
    #pragma unroll
    for (int i = 0; i < 8; i++) {
        int e = tid + i * 256;
        int row = e >> 4, c16 = e & 15;
        uint32_t off = swz((uint32_t)(row * 256 + c16 * 16));
        size_t gq = (size_t)(qt * QTILE + row) * 256 + c16 * 16;
        size_t gb = (size_t)(split_start + row) * 256 + c16 * 16;
        cpa16(sb + SA_HI + off, (const char*)g_x_hi + gq);
        cpa16(sb + SA_LO + off, (const char*)g_x_lo + gq);
        cpa16(sb + SB_HI + off, (const char*)g_train_hi + gb);
        cpa16(sb + SB_LO + off, (const char*)g_train_lo + gb);
    }
    if (tid < 32) cpa16(sb + T2_OFF + tid * 16, (const char*)(g_t2 + split_start) + tid * 16);
    CP_COMMIT();
    #pragma unroll
    for (int j = 0; j < 16; j++) { stv[j * 256 + tid] = FLT_MAX; sti[j * 256 + tid] = 0; }
    float vmax = FLT_MAX; int maxslot = 0;
    CP_WAIT0();
    __syncthreads();

    const int scan_q = tid >> 1, scan_h = tid & 1, s5 = scan_q & 31;

    for (int ch = 0; ch < nch; ch++) {
        const int cb = split_start + ch * CHUNK;
        const int nx = ch + 1;
        float acc[16][4];
        #pragma unroll
        for (int i = 0; i < 16; i++)
            #pragma unroll
            for (int j = 0; j < 4; j++) acc[i][j] = 0.f;

        gemm_pass(sb + SA_HI, sb + SB_HI, athr, bthr, xa, m0, n0, acc);
        gemm_pass(sb + SA_LO, sb + SB_HI, athr, bthr, xa, m0, n0, acc);
        __syncthreads();                       // done reading B_hi
        if (nx < nch) {                        // prefetch B_hi(ch+1) + t2(ch+1)
            const int cbn = split_start + nx * CHUNK;
            #pragma unroll
            for (int i = 0; i < 8; i++) {
                int e = tid + i * 256;
                int row = e >> 4, c16 = e & 15;
                cpa16(sb + SB_HI + swz((uint32_t)(row * 256 + c16 * 16)),
                      (const char*)g_train_hi + (size_t)(cbn + row) * 256 + c16 * 16);
            }
            if (tid < 32) cpa16(sb + T2_OFF + (nx & 1) * 512 + tid * 16,
                                (const char*)(g_t2 + cbn) + tid * 16);
            CP_COMMIT();
        }
        gemm_pass(sb + SA_HI, sb + SB_LO, athr, bthr, xa, m0, n0, acc);
        __syncthreads();                       // done reading B_lo
        if (nx < nch) {                        // prefetch B_lo(ch+1)
            const int cbn = split_start + nx * CHUNK;
            #pragma unroll
            for (int i = 0; i < 8; i++) {
                int e = tid + i * 256;
                int row = e >> 4, c16 = e & 15;
                cpa16(sb + SB_LO + swz((uint32_t)(row * 256 + c16 * 16)),
                      (const char*)g_train_lo + (size_t)(cbn + row) * 256 + c16 * 16);
            }
            CP_COMMIT();
        }

        // write scores: sc = t2 - 2*dot (swizzled float2 tile)
        {
            const float2* t22 = (const float2*)(t2r + (ch & 1) * 128);
            const int tq = lane >> 2, tc = lane & 3;
            #pragma unroll
            for (int i = 0; i < 4; i++) {
                #pragma unroll
                for (int j = 0; j < 4; j++) {
                    int c2 = (n0 >> 1) + j * 4 + tc;
                    float2 t2v = t22[c2];
                    int q0 = m0 + i * 16 + tq;
                    int q1 = q0 + 8;
                    Ds2[q0 * 64 + (c2 ^ (q0 & 31))] =
                        make_float2(fmaf(-2.f, acc[i*4+j][0], t2v.x),
                                    fmaf(-2.f, acc[i*4+j][1], t2v.y));
                    Ds2[q1 * 64 + (c2 ^ (q1 & 31))] =
                        make_float2(fmaf(-2.f, acc[i*4+j][2], t2v.x),
                                    fmaf(-2.f, acc[i*4+j][3], t2v.y));
                }
            }
        }
        __syncthreads();

        // scan: 2 threads per query, 64 cols each
        {
            const float2* rowp = Ds2 + scan_q * 64;
            const int cb2 = cb + scan_h * 64;
            #pragma unroll 4
            for (int cc2 = 0; cc2 < 32; cc2++) {
                int c2 = scan_h * 32 + cc2;
                float2 v2 = rowp[c2 ^ s5];
                int gc = cb2 + cc2 * 2;
                if (gc < split_end && v2.x < vmax)
                    topk_ins(stv, sti, tid, v2.x, gc, vmax, maxslot);
                if (gc + 1 < split_end && v2.y < vmax)
                    topk_ins(stv, sti, tid, v2.y, gc + 1, vmax, maxslot);
            }
        }
        CP_WAIT0();
        __syncthreads();
    }

    // dump per-(query,split) 2x16 candidates
    {
        int q = qt * QTILE + scan_q;
        int base = (q * NSPLIT + split) * 32 + scan_h * 16;
        #pragma unroll
        for (int j = 0; j < 16; j++) {
            g_topd[base + j] = stv[j * 256 + tid];
            g_topi[base + j] = sti[j * 256 + tid];
        }
    }
}

// -------- kernel 3: merge 288 candidates/query, weighted vote --------
__global__ void finalize_kernel(const int* __restrict__ labels,
                                float* __restrict__ pred_out,
                                float* __restrict__ proba_out) {
    int warp = threadIdx.x >> 5, lane = threadIdx.x & 31;
    int q = blockIdx.x * 8 + warp;

    float cv[9]; int ci[9];
    const float* td = g_topd + (size_t)q * (NSPLIT * 32);
    const int*   ti = g_topi + (size_t)q * (NSPLIT * 32);
    #pragma unroll
    for (int t = 0; t < 9; t++) { cv[t] = td[lane + 32*t]; ci[t] = ti[lane + 32*t]; }

    float x2 = g_x2[q];
    float proba[NC], pz[NC];
    #pragma unroll
    for (int c = 0; c < NC; c++) { proba[c] = 0.f; pz[c] = 0.f; }
    bool anyz = false;

    for (int r = 0; r < KNB; r++) {
        float mv = cv[0]; int ms = 0;
        #pragma unroll
        for (int t = 1; t < 9; t++) if (cv[t] < mv) { mv = cv[t]; ms = t; }
        float rv = mv; int ridx = ci[0]; int rlane = lane;
        #pragma unroll
        for (int t = 0; t < 9; t++) if (t == ms) ridx = ci[t];
        #pragma unroll
        for (int o = 16; o > 0; o >>= 1) {
            float ov = __shfl_down_sync(0xffffffffu, rv, o);
            int   oi = __shfl_down_sync(0xffffffffu, ridx, o);
            int   ol = __shfl_down_sync(0xffffffffu, rlane, o);
            if (ov < rv) { rv = ov; ridx = oi; rlane = ol; }
        }
        rv    = __shfl_sync(0xffffffffu, rv, 0);
        ridx  = __shfl_sync(0xffffffffu, ridx, 0);
        rlane = __shfl_sync(0xffffffffu, rlane, 0);
        #pragma unroll
        for (int t = 0; t < 9; t++)
            if (lane == rlane && t == ms) cv[t] = FLT_MAX;

        float d = sqrtf(fmaxf(x2 + rv, 0.0f));
        int lab = labels[ridx];
        if (d <= 0.0f) {
            anyz = true;
            #pragma unroll
            for (int c = 0; c < NC; c++) pz[c] += (lab == c) ? 1.0f : 0.0f;
        } else {
            float w = 1.0f / d;
            #pragma unroll
            for (int c = 0; c < NC; c++) proba[c] += (lab == c) ? w : 0.0f;
        }
    }

    if (anyz) {
        #pragma unroll
        for (int c = 0; c < NC; c++) proba[c] = pz[c];
    }
    float ssum = 0.f;
    #pragma unroll
    for (int c = 0; c < NC; c++) ssum += proba[c];
    if (ssum == 0.f) ssum = 1.f;
    float inv = 1.f / ssum;

    int best = 0; float bv = proba[0];
    #pragma unroll
    for (int c = 1; c < NC; c++) if (proba[c] > bv) { bv = proba[c]; best = c; }

    if (lane == 0) {
        if (pred_out)  pred_out[q] = (float)best;
        if (proba_out) {
            #pragma unroll
            for (int c = 0; c < NC; c++) proba_out[q * NC + c] = proba[c] * inv;
        }
    }
}

// -------- launch --------
extern "C" void kernel_launch(void* const* d_in, const int* in_sizes, int n_in,
                              void* d_out, int out_size) {
    const float* x      = (const float*)d_in[0];
    const float* train  = (const float*)d_in[1];
    const int*   labels = (const int*)d_in[2];
    float* out = (float*)d_out;

    float* pred_out  = nullptr;
    float* proba_out = nullptr;
    if (out_size >= NQ * (NC + 1)) { pred_out = out; proba_out = out + NQ; }
    else if (out_size == NQ * NC)  { proba_out = out; }
    else                           { pred_out = out; }

    cudaFuncSetAttribute(knn_kernel, cudaFuncAttributeMaxDynamicSharedMemorySize, SMEM_TOTAL);

    prep_kernel<<<(MTRAIN + NQ + 7) / 8, 256>>>(x, train);
    knn_kernel<<<dim3(NSPLIT, NQ / QTILE), 256, SMEM_TOTAL>>>();
    finalize_kernel<<<NQ / 8, 256>>>(labels, pred_out, proba_out);
}

// round 7
// speedup vs baseline: 2.7312x; 1.3711x over previous
#include <cuda_runtime.h>
#include <cuda_bf16.h>
#include <float.h>
#include <stdint.h>

#define NQ      2048
#define DIMS    128
#define MTRAIN  100000
#define KNB     16
#define NC      10
#define NSPLIT  9
#define SPLIT   11112
#define QTILE   128
#define CHUNK   128

// smem map (bytes)
#define SA_HI  0                    // 32KB A tile
#define SB(s)  (32768 + (s)*32768)  // 2 x 32KB B tiles
#define DS_OFF 98304                // 64KB score tile
#define T2_OFF 163840               // 2 x 128 floats
#define STV_OFF 164864              // 16 x 256 floats
#define STI_OFF 181248              // 16 x 256 ints
#define SMEM_TOTAL 197632

__device__ float g_t2[MTRAIN];
__device__ float g_x2[NQ];
__device__ __nv_bfloat16 g_train_hi[(size_t)MTRAIN*DIMS];
__device__ __nv_bfloat16 g_x_hi[NQ*DIMS];
__device__ float g_topd[NQ * NSPLIT * 32];
__device__ int   g_topi[NQ * NSPLIT * 32];

__device__ __forceinline__ uint32_t smem_u32(const void* p) {
    uint32_t a;
    asm("{ .reg .u64 t; cvta.to.shared.u64 t, %1; cvt.u32.u64 %0, t; }" : "=r"(a) : "l"(p));
    return a;
}
__device__ __forceinline__ void cpa16(uint32_t dst, const void* src) {
    asm volatile("cp.async.cg.shared.global [%0], [%1], 16;" :: "r"(dst), "l"(src));
}
#define CP_COMMIT() asm volatile("cp.async.commit_group;" ::: "memory")
#define CP_WAIT0()  asm volatile("cp.async.wait_group 0;" ::: "memory")

__device__ __forceinline__ uint32_t swz(uint32_t off) {
    return off ^ ((off >> 4) & 0x70u);
}
__device__ __forceinline__ uint32_t pkbf(__nv_bfloat16 a, __nv_bfloat16 b) {
    return (uint32_t)__bfloat16_as_ushort(a) | ((uint32_t)__bfloat16_as_ushort(b) << 16);
}

// -------- kernel 1: norms + bf16 hi --------
__global__ void prep_kernel(const float* __restrict__ x, const float* __restrict__ train) {
    int warp = (blockIdx.x * blockDim.x + threadIdx.x) >> 5;
    int lane = threadIdx.x & 31;
    if (warp >= MTRAIN + NQ) return;
    const float* src; __nv_bfloat16* dh; float* t2dst;
    if (warp < MTRAIN) {
        src = train + (size_t)warp * DIMS;
        dh = g_train_hi + (size_t)warp * DIMS;
        t2dst = g_t2 + warp;
    } else {
        int q = warp - MTRAIN;
        src = x + (size_t)q * DIMS;
        dh = g_x_hi + (size_t)q * DIMS;
        t2dst = g_x2 + q;
    }
    float4 v = ((const float4*)src)[lane];
    ((uint2*)dh)[lane] = make_uint2(pkbf(__float2bfloat16(v.x), __float2bfloat16(v.y)),
                                    pkbf(__float2bfloat16(v.z), __float2bfloat16(v.w)));
    float s = v.x*v.x + v.y*v.y + v.z*v.z + v.w*v.w;
    #pragma unroll
    for (int o = 16; o > 0; o >>= 1) s += __shfl_down_sync(0xffffffffu, s, o);
    if (lane == 0) *t2dst = s;
}

// one bf16 pass: acc += A(sa) * B(sb)^T over K=128
__device__ __forceinline__ void gemm_pass(uint32_t sa, uint32_t sb,
                                          uint32_t athr, uint32_t bthr, uint32_t xa,
                                          int m0, int n0, float acc[16][4]) {
    #pragma unroll
    for (int kk = 0; kk < 8; kk++) {
        uint32_t a[4][4], b[4][2];
        #pragma unroll
        for (int i = 0; i < 4; i++) {
            uint32_t off = (uint32_t)((m0 + i * 16) * 256) + athr + kk * 32;
            uint32_t ad = sa + (off ^ xa);
            asm volatile("ldmatrix.sync.aligned.m8n8.x4.shared.b16 {%0,%1,%2,%3}, [%4];"
                : "=r"(a[i][0]), "=r"(a[i][1]), "=r"(a[i][2]), "=r"(a[i][3]) : "r"(ad));
        }
        #pragma unroll
        for (int j2 = 0; j2 < 2; j2++) {
            uint32_t off = (uint32_t)(n0 * 256 + j2 * 4096) + bthr + kk * 32;
            uint32_t bd = sb + (off ^ xa);
            asm volatile("ldmatrix.sync.aligned.m8n8.x4.shared.b16 {%0,%1,%2,%3}, [%4];"
                : "=r"(b[j2*2][0]), "=r"(b[j2*2][1]), "=r"(b[j2*2+1][0]), "=r"(b[j2*2+1][1])
                : "r"(bd));
        }
        #pragma unroll
        for (int i = 0; i < 4; i++)
            #pragma unroll
            for (int j = 0; j < 4; j++) {
                float* d = acc[i * 4 + j];
                asm volatile("mma.sync.aligned.m16n8k16.row.col.f32.bf16.bf16.f32 "
                    "{%0,%1,%2,%3}, {%4,%5,%6,%7}, {%8,%9}, {%0,%1,%2,%3};"
                    : "+f"(d[0]), "+f"(d[1]), "+f"(d[2]), "+f"(d[3])
                    : "r"(a[i][0]), "r"(a[i][1]), "r"(a[i][2]), "r"(a[i][3]),
                      "r"(b[j][0]), "r"(b[j][1]));
            }
    }
}

__device__ __forceinline__ void topk_ins(float* stv, int* sti, int tid,
                                         float sc, int gc, float& vmax, int& maxslot) {
    stv[maxslot * 256 + tid] = sc;
    sti[maxslot * 256 + tid] = gc;
    float nm = stv[tid]; int np = 0;
    #pragma unroll
    for (int j = 1; j < 16; j++) {
        float tj = stv[j * 256 + tid];
        if (tj > nm) { nm = tj; np = j; }
    }
    vmax = nm; maxslot = np;
}

// -------- kernel 2: 1-pass bf16 HMMA approx GEMM + fused top-16 --------
__global__ __launch_bounds__(256, 1) void knn_kernel() {
    extern __shared__ char sm[];
    const uint32_t sb = smem_u32(sm);
    float2* Ds2 = (float2*)(sm + DS_OFF);
    float*  t2r = (float*)(sm + T2_OFF);
    float*  stv = (float*)(sm + STV_OFF);
    int*    sti = (int*)(sm + STI_OFF);

    const int tid = threadIdx.x;
    const int wid = tid >> 5;
    const int lane = tid & 31;
    const int split = blockIdx.x;
    const int qt    = blockIdx.y;
    const int split_start = split * SPLIT;
    const int split_end   = min(split_start + SPLIT, MTRAIN);
    const int nch = (split_end - split_start + CHUNK - 1) / CHUNK;

    const int m0 = (wid >> 2) * 64;
    const int n0 = (wid & 3) * 32;
    const uint32_t xa   = (uint32_t)(lane & 7) << 4;
    const uint32_t athr = (uint32_t)((lane & 15) * 256 + ((lane >> 4) & 1) * 16);
    const uint32_t bthr = (uint32_t)((lane & 7) * 256 + ((lane >> 4) & 1) * 2048
                                     + ((lane >> 3) & 1) * 16);

    // prologue: A hi + B(0) + t2(0)
    #pragma unroll
    for (int i = 0; i < 4; i++) {
        int e = tid + i * 256;
        int row = e >> 3, c16 = e & 7;        // 128 rows x 8 x 16B = 32KB, 2 halves
        uint32_t off0 = swz((uint32_t)(row * 256 + c16 * 16));
        uint32_t off1 = swz((uint32_t)(row * 256 + (c16 + 8) * 16));
        size_t gq = (size_t)(qt * QTILE + row) * 256;
        size_t gb = (size_t)(split_start + row) * 256;
        cpa16(sb + SA_HI + off0, (const char*)g_x_hi + gq + c16 * 16);
        cpa16(sb + SA_HI + off1, (const char*)g_x_hi + gq + (c16 + 8) * 16);
        cpa16(sb + SB(0) + off0, (const char*)g_train_hi + gb + c16 * 16);
        cpa16(sb + SB(0) + off1, (const char*)g_train_hi + gb + (c16 + 8) * 16);
    }
    if (tid < 32) cpa16(sb + T2_OFF + tid * 16, (const char*)(g_t2 + split_start) + tid * 16);
    CP_COMMIT();
    #pragma unroll
    for (int j = 0; j < 16; j++) { stv[j * 256 + tid] = FLT_MAX; sti[j * 256 + tid] = 0; }
    float vmax = FLT_MAX; int maxslot = 0;
    CP_WAIT0();
    __syncthreads();

    const int scan_q = tid >> 1, scan_h = tid & 1, s5 = scan_q & 31;

    for (int ch = 0; ch < nch; ch++) {
        const int cb = split_start + ch * CHUNK;
        const int nx = ch + 1;
        const int s = ch & 1;

        // prefetch B(ch+1) + t2(ch+1) while this chunk computes
        if (nx < nch) {
            const int cbn = split_start + nx * CHUNK;
            #pragma unroll
            for (int i = 0; i < 8; i++) {
                int e = tid + i * 256;
                int row = e >> 4, c16 = e & 15;
                cpa16(sb + SB(nx & 1) + swz((uint32_t)(row * 256 + c16 * 16)),
                      (const char*)g_train_hi + (size_t)(cbn + row) * 256 + c16 * 16);
            }
            if (tid < 32) cpa16(sb + T2_OFF + (nx & 1) * 512 + tid * 16,
                                (const char*)(g_t2 + cbn) + tid * 16);
            CP_COMMIT();
        }

        float acc[16][4];
        #pragma unroll
        for (int i = 0; i < 16; i++)
            #pragma unroll
            for (int j = 0; j < 4; j++) acc[i][j] = 0.f;

        gemm_pass(sb + SA_HI, sb + SB(s), athr, bthr, xa, m0, n0, acc);

        // epilogue: sc = t2 - 2*dot into swizzled float2 tile
        {
            const float2* t22 = (const float2*)(t2r + (ch & 1) * 128);
            const int tq = lane >> 2, tc = lane & 3;
            #pragma unroll
            for (int i = 0; i < 4; i++) {
                #pragma unroll
                for (int j = 0; j < 4; j++) {
                    int c2 = (n0 >> 1) + j * 4 + tc;
                    float2 t2v = t22[c2];
                    int q0 = m0 + i * 16 + tq;
                    int q1 = q0 + 8;
                    Ds2[q0 * 64 + (c2 ^ (q0 & 31))] =
                        make_float2(fmaf(-2.f, acc[i*4+j][0], t2v.x),
                                    fmaf(-2.f, acc[i*4+j][1], t2v.y));
                    Ds2[q1 * 64 + (c2 ^ (q1 & 31))] =
                        make_float2(fmaf(-2.f, acc[i*4+j][2], t2v.x),
                                    fmaf(-2.f, acc[i*4+j][3], t2v.y));
                }
            }
        }
        __syncthreads();

        // scan: 2 threads per query, 64 candidates each
        {
            const float2* rowp = Ds2 + scan_q * 64;
            const int cb2 = cb + scan_h * 64;
            #pragma unroll 4
            for (int cc2 = 0; cc2 < 32; cc2++) {
                int c2 = scan_h * 32 + cc2;
                float2 v2 = rowp[c2 ^ s5];
                int gc = cb2 + cc2 * 2;
                if (gc < split_end && v2.x < vmax)
                    topk_ins(stv, sti, tid, v2.x, gc, vmax, maxslot);
                if (gc + 1 < split_end && v2.y < vmax)
                    topk_ins(stv, sti, tid, v2.y, gc + 1, vmax, maxslot);
            }
        }
        CP_WAIT0();
        __syncthreads();
    }

    // dump per-(query,split) 2x16 approx candidates
    {
        int q = qt * QTILE + scan_q;
        int base = (q * NSPLIT + split) * 32 + scan_h * 16;
        #pragma unroll
        for (int j = 0; j < 16; j++) {
            g_topd[base + j] = stv[j * 256 + tid];
            g_topi[base + j] = sti[j * 256 + tid];
        }
    }
}

// -------- kernel 3: merge 288 approx -> top-32 -> exact fp32 refine -> vote --------
__global__ void finalize_kernel(const float* __restrict__ x,
                                const float* __restrict__ train,
                                const int* __restrict__ labels,
                                float* __restrict__ pred_out,
                                float* __restrict__ proba_out) {
    __shared__ float xs[8][128];
    int warp = threadIdx.x >> 5, lane = threadIdx.x & 31;
    int q = blockIdx.x * 8 + warp;

    // load 288 approx candidates
    float cv[9]; int ci[9];
    const float* td = g_topd + (size_t)q * (NSPLIT * 32);
    const int*   ti = g_topi + (size_t)q * (NSPLIT * 32);
    #pragma unroll
    for (int t = 0; t < 9; t++) { cv[t] = td[lane + 32*t]; ci[t] = ti[lane + 32*t]; }

    // select approx-top-32; winner of round r kept by lane r
    int myidx = 0;
    for (int r = 0; r < 32; r++) {
        float mv = cv[0]; int ms = 0;
        #pragma unroll
        for (int t = 1; t < 9; t++) if (cv[t] < mv) { mv = cv[t]; ms = t; }
        float rv = mv; int ridx = ci[0]; int rlane = lane;
        #pragma unroll
        for (int t = 0; t < 9; t++) if (t == ms) ridx = ci[t];
        #pragma unroll
        for (int o = 16; o > 0; o >>= 1) {
            float ov = __shfl_down_sync(0xffffffffu, rv, o);
            int   oi = __shfl_down_sync(0xffffffffu, ridx, o);
            int   ol = __shfl_down_sync(0xffffffffu, rlane, o);
            if (ov < rv) { rv = ov; ridx = oi; rlane = ol; }
        }
        ridx  = __shfl_sync(0xffffffffu, ridx, 0);
        rlane = __shfl_sync(0xffffffffu, rlane, 0);
        if (lane == r) myidx = ridx;
        #pragma unroll
        for (int t = 0; t < 9; t++)
            if (lane == rlane && t == ms) cv[t] = FLT_MAX;
    }

    // exact fp32 distance for my candidate
    ((float4*)xs[warp])[lane] = ((const float4*)(x + (size_t)q * DIMS))[lane];
    __syncwarp();
    const float4* t4 = (const float4*)(train + (size_t)myidx * DIMS);
    const float4* x4 = (const float4*)xs[warp];
    float dot = 0.f;
    #pragma unroll 8
    for (int i = 0; i < 32; i++) {
        float4 tv = t4[i], xv = x4[i];
        dot += xv.x*tv.x + xv.y*tv.y + xv.z*tv.z + xv.w*tv.w;
    }
    float d2 = g_x2[q] + g_t2[myidx] - 2.0f * dot;
    float myv = sqrtf(fmaxf(d2, 0.0f));
    int   lab = labels[myidx];

    // exact top-16 of 32 + weighted vote
    float proba[NC], pz[NC];
    #pragma unroll
    for (int c = 0; c < NC; c++) { proba[c] = 0.f; pz[c] = 0.f; }
    bool anyz = false;

    for (int r = 0; r < KNB; r++) {
        float rv = myv; int rlab = lab; int rlane = lane;
        #pragma unroll
        for (int o = 16; o > 0; o >>= 1) {
            float ov = __shfl_down_sync(0xffffffffu, rv, o);
            int   oi = __shfl_down_sync(0xffffffffu, rlab, o);
            int   ol = __shfl_down_sync(0xffffffffu, rlane, o);
            if (ov < rv) { rv = ov; rlab = oi; rlane = ol; }
        }
        rv    = __shfl_sync(0xffffffffu, rv, 0);
        rlab  = __shfl_sync(0xffffffffu, rlab, 0);
        rlane = __shfl_sync(0xffffffffu, rlane, 0);
        if (lane == rlane) myv = FLT_MAX;

        if (rv <= 0.0f) {
            anyz = true;
            #pragma unroll
            for (int c = 0; c < NC; c++) pz[c] += (rlab == c) ? 1.0f : 0.0f;
        } else {
            float w = 1.0f / rv;
            #pragma unroll
            for (int c = 0; c < NC; c++) proba[c] += (rlab == c) ? w : 0.0f;
        }
    }

    if (anyz) {
        #pragma unroll
        for (int c = 0; c < NC; c++) proba[c] = pz[c];
    }
    float ssum = 0.f;
    #pragma unroll
    for (int c = 0; c < NC; c++) ssum += proba[c];
    if (ssum == 0.f) ssum = 1.f;
    float inv = 1.f / ssum;

    int best = 0; float bv = proba[0];
    #pragma unroll
    for (int c = 1; c < NC; c++) if (proba[c] > bv) { bv = proba[c]; best = c; }

    if (lane == 0) {
        if (pred_out)  pred_out[q] = (float)best;
        if (proba_out) {
            #pragma unroll
            for (int c = 0; c < NC; c++) proba_out[q * NC + c] = proba[c] * inv;
        }
    }
}

// -------- launch --------
extern "C" void kernel_launch(void* const* d_in, const int* in_sizes, int n_in,
                              void* d_out, int out_size) {
    const float* x      = (const float*)d_in[0];
    const float* train  = (const float*)d_in[1];
    const int*   labels = (const int*)d_in[2];
    float* out = (float*)d_out;

    float* pred_out  = nullptr;
    float* proba_out = nullptr;
    if (out_size >= NQ * (NC + 1)) { pred_out = out; proba_out = out + NQ; }
    else if (out_size == NQ * NC)  { proba_out = out; }
    else                           { pred_out = out; }

    cudaFuncSetAttribute(knn_kernel, cudaFuncAttributeMaxDynamicSharedMemorySize, SMEM_TOTAL);

    prep_kernel<<<(MTRAIN + NQ + 7) / 8, 256>>>(x, train);
    knn_kernel<<<dim3(NSPLIT, NQ / QTILE), 256, SMEM_TOTAL>>>();
    finalize_kernel<<<NQ / 8, 256>>>(x, train, labels, pred_out, proba_out);
}